// round 1
// baseline (speedup 1.0000x reference)
#include <cuda_runtime.h>
#include <math.h>

#define NI   128      // instances
#define Hh   400
#define Ww   400
#define MS   28
#define CT   80
#define CS   53
#define HW   (Hh*Ww)          // 160000
#define NCH  (CS + NI)        // 181
#define HG   1600
#define IGNORE_LBL 255

#define LOSS_BLOCKS (HW/256)  // 625

__device__ float g_partial[LOSS_BLOCKS];
__device__ float g_count[LOSS_BLOCKS];

// ---------------------------------------------------------------------------
// Thing channels: out[(CS+n)*HW + y*W + x] = mask_bilinear + sem_logit
// ---------------------------------------------------------------------------
__global__ __launch_bounds__(256)
void thing_kernel(const float* __restrict__ mask_logits,   // [N,CT,MS,MS]
                  const float* __restrict__ thing_logit,   // [CT,H,W]
                  const float* __restrict__ bbox,          // [N,4]
                  const int*   __restrict__ cls_idx,       // [N]
                  float* __restrict__ out)                 // pan_logit base
{
    const int n = blockIdx.z;
    const float b0 = bbox[n*4+0], b1 = bbox[n*4+1];
    const float b2 = bbox[n*4+2], b3 = bbox[n*4+3];

    // floor(bbox/4) box (feature px)
    const int x0b = (int)floorf(b0 * 0.25f);
    const int y0b = (int)floorf(b1 * 0.25f);
    const int x2b = (int)floorf(b2 * 0.25f);
    const int y2b = (int)floorf(b3 * 0.25f);
    const int hh = y2b - y0b + 1;
    const int ww = x2b - x0b + 1;

    // sem rect (truncating casts; rintf == jnp.round half-to-even)
    const int cx1 = (int)(b0 * 0.25f);
    const int cy1 = (int)(b1 * 0.25f);
    const int cx2 = (int)(rintf(b2 * 0.25f) + 1.0f);
    const int cy2 = (int)(rintf(b3 * 0.25f) + 1.0f);

    const int cls = cls_idx[n];

    __shared__ float tile[MS*MS];
    const int bx0 = blockIdx.x * 32;
    const int by0 = blockIdx.y * 8;

    // load mask tile only if this block overlaps the mask box
    const bool overlap = !((bx0 + 31) < x0b || bx0 > x2b ||
                           (by0 + 7)  < y0b || by0 > y2b);
    if (overlap) {
        const float* ml = mask_logits + ((size_t)n * CT + cls) * (MS*MS);
        const int t = threadIdx.y * 32 + threadIdx.x;
        for (int i = t; i < MS*MS; i += 256) tile[i] = ml[i];
    }
    __syncthreads();

    const int x = bx0 + threadIdx.x;
    const int y = by0 + threadIdx.y;
    if (x >= Ww || y >= Hh) return;

    float v = 0.0f;

    if (x >= x0b && x <= x2b && y >= y0b && y <= y2b) {
        // bilinear sample of 28x28 tile (align_corners=False semantics)
        const float sy = ((float)(y - y0b) + 0.5f) * ((float)MS / (float)hh) - 0.5f;
        const float fy = floorf(sy);
        const float ty = sy - fy;
        int i0 = (int)fy;       i0 = min(max(i0, 0), MS-1);
        int i1 = (int)fy + 1;   i1 = min(max(i1, 0), MS-1);

        const float sx = ((float)(x - x0b) + 0.5f) * ((float)MS / (float)ww) - 0.5f;
        const float fx = floorf(sx);
        const float tx = sx - fx;
        int j0 = (int)fx;       j0 = min(max(j0, 0), MS-1);
        int j1 = (int)fx + 1;   j1 = min(max(j1, 0), MS-1);

        const float r00 = tile[i0*MS + j0];
        const float r10 = tile[i1*MS + j0];
        const float r01 = tile[i0*MS + j1];
        const float r11 = tile[i1*MS + j1];
        const float c0 = r00 * (1.0f - ty) + r10 * ty;
        const float c1 = r01 * (1.0f - ty) + r11 * ty;
        v = c0 * (1.0f - tx) + c1 * tx;
    }

    if (x >= cx1 && x < cx2 && y >= cy1 && y < cy2) {
        v += thing_logit[(size_t)cls * HW + y * Ww + x];
    }

    out[(size_t)(CS + n) * HW + y * Ww + x] = v;
}

// ---------------------------------------------------------------------------
// Loss: per-pixel logsumexp over 181 channels of pan_logit, NLL at target,
// block-deterministic partial sums.
// ---------------------------------------------------------------------------
__global__ __launch_bounds__(256)
void loss_kernel(const float* __restrict__ pan,      // [NCH,H,W]
                 const int*   __restrict__ gt)       // [HG,WG]
{
    const int p = blockIdx.x * 256 + threadIdx.x;    // < HW exactly
    const int y = p / Ww;
    const int x = p - y * Ww;

    const int g = gt[(size_t)(y * 4) * HG + (x * 4)];
    int tgt = g; tgt = min(max(tgt, 0), NCH - 1);

    const float* ptr = pan + p;
    float s  = 0.0f;
    float tv = 0.0f;
    #pragma unroll 4
    for (int c = 0; c < NCH; ++c) {
        const float v = ptr[(size_t)c * HW];
        s += expf(v);
        if (c == tgt) tv = v;
    }
    const float nll = logf(s) - tv;
    const bool valid = (g != IGNORE_LBL);
    float contrib = valid ? nll : 0.0f;
    float cnt     = valid ? 1.0f : 0.0f;

    // block reduce (deterministic)
    __shared__ float ssum[256];
    __shared__ float scnt[256];
    const int tid = threadIdx.x;
    ssum[tid] = contrib;
    scnt[tid] = cnt;
    __syncthreads();
    for (int off = 128; off > 0; off >>= 1) {
        if (tid < off) {
            ssum[tid] += ssum[tid + off];
            scnt[tid] += scnt[tid + off];
        }
        __syncthreads();
    }
    if (tid == 0) {
        g_partial[blockIdx.x] = ssum[0];
        g_count[blockIdx.x]   = scnt[0];
    }
}

__global__ __launch_bounds__(256)
void finalize_kernel(float* __restrict__ loss_out)
{
    __shared__ double sd[256];
    __shared__ double sc[256];
    const int tid = threadIdx.x;
    double s = 0.0, c = 0.0;
    for (int i = tid; i < LOSS_BLOCKS; i += 256) {
        s += (double)g_partial[i];
        c += (double)g_count[i];
    }
    sd[tid] = s; sc[tid] = c;
    __syncthreads();
    for (int off = 128; off > 0; off >>= 1) {
        if (tid < off) { sd[tid] += sd[tid + off]; sc[tid] += sc[tid + off]; }
        __syncthreads();
    }
    if (tid == 0) {
        const double denom = sd[0] >= 0.0 ? fmax(sc[0], 1.0) : fmax(sc[0], 1.0);
        *loss_out = (float)(sd[0] / denom);
    }
}

// ---------------------------------------------------------------------------
extern "C" void kernel_launch(void* const* d_in, const int* in_sizes, int n_in,
                              void* d_out, int out_size)
{
    const float* mask_logits = (const float*)d_in[0];   // [128,80,28,28]
    const float* stuff_logit = (const float*)d_in[1];   // [53,400,400]
    const float* thing_logit = (const float*)d_in[2];   // [80,400,400]
    const float* bbox        = (const float*)d_in[3];   // [128,4]
    const int*   cls_idx     = (const int*)  d_in[4];   // [128]
    const int*   gt          = (const int*)  d_in[5];   // [1600,1600]

    float* out = (float*)d_out;

    // stuff channels: straight copy into pan_logit[0:53]
    cudaMemcpyAsync(out, stuff_logit, (size_t)CS * HW * sizeof(float),
                    cudaMemcpyDeviceToDevice, 0);

    // thing channels
    dim3 blk(32, 8, 1);
    dim3 grd((Ww + 31) / 32, (Hh + 7) / 8, NI);
    thing_kernel<<<grd, blk>>>(mask_logits, thing_logit, bbox, cls_idx, out);

    // loss
    loss_kernel<<<LOSS_BLOCKS, 256>>>(out, gt);
    finalize_kernel<<<1, 256>>>(out + (size_t)out_size - 1);
}

// round 2
// speedup vs baseline: 1.4957x; 1.4957x over previous
#include <cuda_runtime.h>
#include <math.h>

#define NI   128
#define Hh   400
#define Ww   400
#define MS   28
#define CT   80
#define CS   53
#define HW   (Hh*Ww)          // 160000
#define NCH  (CS + NI)        // 181
#define HG   1600
#define IGNORE_LBL 255

#define LOSS_THREADS (HW/4)         // 40000
#define LOSS_BLOCKS  ((LOSS_THREADS + 255)/256)   // 157

__device__ float g_partial[LOSS_BLOCKS];
__device__ float g_count[LOSS_BLOCKS];

// ---------------------------------------------------------------------------
// Init: pan_logit[0:CS] = stuff_logit, pan_logit[CS:] = 0   (float4 stores)
// ---------------------------------------------------------------------------
__global__ __launch_bounds__(256)
void init_kernel(const float4* __restrict__ stuff4, float4* __restrict__ out4)
{
    const int total4 = NCH * HW / 4;          // 7,240,000
    const int stuff_total4 = CS * HW / 4;     // 2,120,000
    int i = blockIdx.x * 256 + threadIdx.x;
    if (i >= total4) return;
    float4 v;
    if (i < stuff_total4) v = stuff4[i];
    else { v.x = 0.f; v.y = 0.f; v.z = 0.f; v.w = 0.f; }
    out4[i] = v;
}

// ---------------------------------------------------------------------------
// Thing channels, box-local grid: grid (4,13,NI), block (32,8)
// Covers the union rect of mask box and sem rect (max ~102x102 feature px).
// ---------------------------------------------------------------------------
__global__ __launch_bounds__(256)
void thing_kernel(const float* __restrict__ mask_logits,   // [N,CT,MS,MS]
                  const float* __restrict__ thing_logit,   // [CT,H,W]
                  const float* __restrict__ bbox,          // [N,4]
                  const int*   __restrict__ cls_idx,       // [N]
                  float* __restrict__ out)
{
    const int n = blockIdx.z;
    const float b0 = bbox[n*4+0], b1 = bbox[n*4+1];
    const float b2 = bbox[n*4+2], b3 = bbox[n*4+3];

    const int x0b = (int)floorf(b0 * 0.25f);
    const int y0b = (int)floorf(b1 * 0.25f);
    const int x2b = (int)floorf(b2 * 0.25f);
    const int y2b = (int)floorf(b3 * 0.25f);
    const int hh = y2b - y0b + 1;
    const int ww = x2b - x0b + 1;

    const int cx1 = (int)(b0 * 0.25f);
    const int cy1 = (int)(b1 * 0.25f);
    const int cx2 = (int)(rintf(b2 * 0.25f) + 1.0f);
    const int cy2 = (int)(rintf(b3 * 0.25f) + 1.0f);

    // union rect (clipped to image)
    const int rx0 = max(min(x0b, cx1), 0);
    const int ry0 = max(min(y0b, cy1), 0);
    const int rx1 = min(max(x2b, cx2 - 1), Ww - 1);
    const int ry1 = min(max(y2b, cy2 - 1), Hh - 1);

    const int cls = cls_idx[n];

    __shared__ float tile[MS*MS];
    {
        const float* ml = mask_logits + ((size_t)n * CT + cls) * (MS*MS);
        const int t = threadIdx.y * 32 + threadIdx.x;
        for (int i = t; i < MS*MS; i += 256) tile[i] = ml[i];
    }
    __syncthreads();

    const int x = rx0 + blockIdx.x * 32 + threadIdx.x;
    const int y = ry0 + blockIdx.y * 8  + threadIdx.y;
    if (x > rx1 || y > ry1) return;

    float v = 0.0f;

    if (x >= x0b && x <= x2b && y >= y0b && y <= y2b) {
        const float sy = ((float)(y - y0b) + 0.5f) * ((float)MS / (float)hh) - 0.5f;
        const float fy = floorf(sy);
        const float ty = sy - fy;
        int i0 = (int)fy;       i0 = min(max(i0, 0), MS-1);
        int i1 = (int)fy + 1;   i1 = min(max(i1, 0), MS-1);

        const float sx = ((float)(x - x0b) + 0.5f) * ((float)MS / (float)ww) - 0.5f;
        const float fx = floorf(sx);
        const float tx = sx - fx;
        int j0 = (int)fx;       j0 = min(max(j0, 0), MS-1);
        int j1 = (int)fx + 1;   j1 = min(max(j1, 0), MS-1);

        const float r00 = tile[i0*MS + j0];
        const float r10 = tile[i1*MS + j0];
        const float r01 = tile[i0*MS + j1];
        const float r11 = tile[i1*MS + j1];
        const float c0 = r00 * (1.0f - ty) + r10 * ty;
        const float c1 = r01 * (1.0f - ty) + r11 * ty;
        v = c0 * (1.0f - tx) + c1 * tx;
    }

    if (x >= cx1 && x < cx2 && y >= cy1 && y < cy2) {
        v += thing_logit[(size_t)cls * HW + y * Ww + x];
    }

    out[(size_t)(CS + n) * HW + y * Ww + x] = v;
}

// ---------------------------------------------------------------------------
// Loss: 4 pixels/thread, float4 channel loads, __expf, single-pass logsumexp.
// ---------------------------------------------------------------------------
__global__ __launch_bounds__(256)
void loss_kernel(const float* __restrict__ pan,      // [NCH,H,W]
                 const int*   __restrict__ gt)       // [HG,WG]
{
    const int t4 = blockIdx.x * 256 + threadIdx.x;
    float contrib = 0.0f, cnt = 0.0f;

    if (t4 < LOSS_THREADS) {
        const int p = t4 * 4;                 // 4 consecutive pixels, same row
        const int y = p / Ww;
        const int x = p - y * Ww;

        int g0 = gt[(size_t)(y*4) * HG + (x+0)*4];
        int g1 = gt[(size_t)(y*4) * HG + (x+1)*4];
        int g2 = gt[(size_t)(y*4) * HG + (x+2)*4];
        int g3 = gt[(size_t)(y*4) * HG + (x+3)*4];

        const float4* ptr = (const float4*)(pan + p);
        float s0 = 0.f, s1 = 0.f, s2 = 0.f, s3 = 0.f;
        #pragma unroll 4
        for (int c = 0; c < NCH; ++c) {
            const float4 v = ptr[(size_t)c * (HW/4)];
            s0 += __expf(v.x);
            s1 += __expf(v.y);
            s2 += __expf(v.z);
            s3 += __expf(v.w);
        }

        const int t0 = min(max(g0, 0), NCH-1);
        const int t1 = min(max(g1, 0), NCH-1);
        const int t2 = min(max(g2, 0), NCH-1);
        const int t3 = min(max(g3, 0), NCH-1);
        const float tv0 = pan[(size_t)t0 * HW + p + 0];
        const float tv1 = pan[(size_t)t1 * HW + p + 1];
        const float tv2 = pan[(size_t)t2 * HW + p + 2];
        const float tv3 = pan[(size_t)t3 * HW + p + 3];

        if (g0 != IGNORE_LBL) { contrib += logf(s0) - tv0; cnt += 1.f; }
        if (g1 != IGNORE_LBL) { contrib += logf(s1) - tv1; cnt += 1.f; }
        if (g2 != IGNORE_LBL) { contrib += logf(s2) - tv2; cnt += 1.f; }
        if (g3 != IGNORE_LBL) { contrib += logf(s3) - tv3; cnt += 1.f; }
    }

    __shared__ float ssum[256];
    __shared__ float scnt[256];
    const int tid = threadIdx.x;
    ssum[tid] = contrib;
    scnt[tid] = cnt;
    __syncthreads();
    for (int off = 128; off > 0; off >>= 1) {
        if (tid < off) { ssum[tid] += ssum[tid+off]; scnt[tid] += scnt[tid+off]; }
        __syncthreads();
    }
    if (tid == 0) {
        g_partial[blockIdx.x] = ssum[0];
        g_count[blockIdx.x]   = scnt[0];
    }
}

__global__ __launch_bounds__(256)
void finalize_kernel(float* __restrict__ loss_out)
{
    __shared__ double sd[256];
    __shared__ double sc[256];
    const int tid = threadIdx.x;
    double s = 0.0, c = 0.0;
    for (int i = tid; i < LOSS_BLOCKS; i += 256) {
        s += (double)g_partial[i];
        c += (double)g_count[i];
    }
    sd[tid] = s; sc[tid] = c;
    __syncthreads();
    for (int off = 128; off > 0; off >>= 1) {
        if (tid < off) { sd[tid] += sd[tid+off]; sc[tid] += sc[tid+off]; }
        __syncthreads();
    }
    if (tid == 0) *loss_out = (float)(sd[0] / fmax(sc[0], 1.0));
}

// ---------------------------------------------------------------------------
extern "C" void kernel_launch(void* const* d_in, const int* in_sizes, int n_in,
                              void* d_out, int out_size)
{
    const float* mask_logits = (const float*)d_in[0];
    const float* stuff_logit = (const float*)d_in[1];
    const float* thing_logit = (const float*)d_in[2];
    const float* bbox        = (const float*)d_in[3];
    const int*   cls_idx     = (const int*)  d_in[4];
    const int*   gt          = (const int*)  d_in[5];

    float* out = (float*)d_out;

    const int total4 = NCH * HW / 4;
    init_kernel<<<(total4 + 255)/256, 256>>>((const float4*)stuff_logit,
                                             (float4*)out);

    dim3 blk(32, 8, 1);
    dim3 grd(4, 13, NI);
    thing_kernel<<<grd, blk>>>(mask_logits, thing_logit, bbox, cls_idx, out);

    loss_kernel<<<LOSS_BLOCKS, 256>>>(out, gt);
    finalize_kernel<<<1, 256>>>(out + (size_t)out_size - 1);
}

// round 3
// speedup vs baseline: 1.4997x; 1.0026x over previous
#include <cuda_runtime.h>
#include <math.h>

#define NI   128
#define Hh   400
#define Ww   400
#define MS   28
#define CT   80
#define CS   53
#define HW   (Hh*Ww)          // 160000
#define NCH  (CS + NI)        // 181
#define HG   1600
#define IGNORE_LBL 255

#define LOSS_THREADS (HW/4)         // 40000
#define LOSS_BLOCKS  ((LOSS_THREADS + 255)/256)   // 157

__device__ float g_partial[LOSS_BLOCKS];
__device__ float g_count[LOSS_BLOCKS];

// ---------------------------------------------------------------------------
// Init: pan_logit[0:CS] = stuff_logit, pan_logit[CS:] = 0   (float4 stores)
// ---------------------------------------------------------------------------
__global__ __launch_bounds__(256)
void init_kernel(const float4* __restrict__ stuff4, float4* __restrict__ out4)
{
    const int total4 = NCH * HW / 4;          // 7,240,000
    const int stuff_total4 = CS * HW / 4;     // 2,120,000
    int i = blockIdx.x * 256 + threadIdx.x;
    if (i >= total4) return;
    float4 v;
    if (i < stuff_total4) v = stuff4[i];
    else { v.x = 0.f; v.y = 0.f; v.z = 0.f; v.w = 0.f; }
    out4[i] = v;
}

// ---------------------------------------------------------------------------
// Thing channels, box-local grid: grid (4,13,NI), block (32,8)
// Covers the union rect of mask box and sem rect (max ~102x102 feature px).
// ---------------------------------------------------------------------------
__global__ __launch_bounds__(256)
void thing_kernel(const float* __restrict__ mask_logits,   // [N,CT,MS,MS]
                  const float* __restrict__ thing_logit,   // [CT,H,W]
                  const float* __restrict__ bbox,          // [N,4]
                  const int*   __restrict__ cls_idx,       // [N]
                  float* __restrict__ out)
{
    const int n = blockIdx.z;
    const float b0 = bbox[n*4+0], b1 = bbox[n*4+1];
    const float b2 = bbox[n*4+2], b3 = bbox[n*4+3];

    const int x0b = (int)floorf(b0 * 0.25f);
    const int y0b = (int)floorf(b1 * 0.25f);
    const int x2b = (int)floorf(b2 * 0.25f);
    const int y2b = (int)floorf(b3 * 0.25f);
    const int hh = y2b - y0b + 1;
    const int ww = x2b - x0b + 1;

    const int cx1 = (int)(b0 * 0.25f);
    const int cy1 = (int)(b1 * 0.25f);
    const int cx2 = (int)(rintf(b2 * 0.25f) + 1.0f);
    const int cy2 = (int)(rintf(b3 * 0.25f) + 1.0f);

    // union rect (clipped to image)
    const int rx0 = max(min(x0b, cx1), 0);
    const int ry0 = max(min(y0b, cy1), 0);
    const int rx1 = min(max(x2b, cx2 - 1), Ww - 1);
    const int ry1 = min(max(y2b, cy2 - 1), Hh - 1);

    const int cls = cls_idx[n];

    __shared__ float tile[MS*MS];
    {
        const float* ml = mask_logits + ((size_t)n * CT + cls) * (MS*MS);
        const int t = threadIdx.y * 32 + threadIdx.x;
        for (int i = t; i < MS*MS; i += 256) tile[i] = ml[i];
    }
    __syncthreads();

    const int x = rx0 + blockIdx.x * 32 + threadIdx.x;
    const int y = ry0 + blockIdx.y * 8  + threadIdx.y;
    if (x > rx1 || y > ry1) return;

    float v = 0.0f;

    if (x >= x0b && x <= x2b && y >= y0b && y <= y2b) {
        const float sy = ((float)(y - y0b) + 0.5f) * ((float)MS / (float)hh) - 0.5f;
        const float fy = floorf(sy);
        const float ty = sy - fy;
        int i0 = (int)fy;       i0 = min(max(i0, 0), MS-1);
        int i1 = (int)fy + 1;   i1 = min(max(i1, 0), MS-1);

        const float sx = ((float)(x - x0b) + 0.5f) * ((float)MS / (float)ww) - 0.5f;
        const float fx = floorf(sx);
        const float tx = sx - fx;
        int j0 = (int)fx;       j0 = min(max(j0, 0), MS-1);
        int j1 = (int)fx + 1;   j1 = min(max(j1, 0), MS-1);

        const float r00 = tile[i0*MS + j0];
        const float r10 = tile[i1*MS + j0];
        const float r01 = tile[i0*MS + j1];
        const float r11 = tile[i1*MS + j1];
        const float c0 = r00 * (1.0f - ty) + r10 * ty;
        const float c1 = r01 * (1.0f - ty) + r11 * ty;
        v = c0 * (1.0f - tx) + c1 * tx;
    }

    if (x >= cx1 && x < cx2 && y >= cy1 && y < cy2) {
        v += thing_logit[(size_t)cls * HW + y * Ww + x];
    }

    out[(size_t)(CS + n) * HW + y * Ww + x] = v;
}

// ---------------------------------------------------------------------------
// Loss: 4 pixels/thread, float4 channel loads, __expf, single-pass logsumexp.
// ---------------------------------------------------------------------------
__global__ __launch_bounds__(256)
void loss_kernel(const float* __restrict__ pan,      // [NCH,H,W]
                 const int*   __restrict__ gt)       // [HG,WG]
{
    const int t4 = blockIdx.x * 256 + threadIdx.x;
    float contrib = 0.0f, cnt = 0.0f;

    if (t4 < LOSS_THREADS) {
        const int p = t4 * 4;                 // 4 consecutive pixels, same row
        const int y = p / Ww;
        const int x = p - y * Ww;

        int g0 = gt[(size_t)(y*4) * HG + (x+0)*4];
        int g1 = gt[(size_t)(y*4) * HG + (x+1)*4];
        int g2 = gt[(size_t)(y*4) * HG + (x+2)*4];
        int g3 = gt[(size_t)(y*4) * HG + (x+3)*4];

        const float4* ptr = (const float4*)(pan + p);
        float s0 = 0.f, s1 = 0.f, s2 = 0.f, s3 = 0.f;
        #pragma unroll 4
        for (int c = 0; c < NCH; ++c) {
            const float4 v = ptr[(size_t)c * (HW/4)];
            s0 += __expf(v.x);
            s1 += __expf(v.y);
            s2 += __expf(v.z);
            s3 += __expf(v.w);
        }

        const int t0 = min(max(g0, 0), NCH-1);
        const int t1 = min(max(g1, 0), NCH-1);
        const int t2 = min(max(g2, 0), NCH-1);
        const int t3 = min(max(g3, 0), NCH-1);
        const float tv0 = pan[(size_t)t0 * HW + p + 0];
        const float tv1 = pan[(size_t)t1 * HW + p + 1];
        const float tv2 = pan[(size_t)t2 * HW + p + 2];
        const float tv3 = pan[(size_t)t3 * HW + p + 3];

        if (g0 != IGNORE_LBL) { contrib += logf(s0) - tv0; cnt += 1.f; }
        if (g1 != IGNORE_LBL) { contrib += logf(s1) - tv1; cnt += 1.f; }
        if (g2 != IGNORE_LBL) { contrib += logf(s2) - tv2; cnt += 1.f; }
        if (g3 != IGNORE_LBL) { contrib += logf(s3) - tv3; cnt += 1.f; }
    }

    __shared__ float ssum[256];
    __shared__ float scnt[256];
    const int tid = threadIdx.x;
    ssum[tid] = contrib;
    scnt[tid] = cnt;
    __syncthreads();
    for (int off = 128; off > 0; off >>= 1) {
        if (tid < off) { ssum[tid] += ssum[tid+off]; scnt[tid] += scnt[tid+off]; }
        __syncthreads();
    }
    if (tid == 0) {
        g_partial[blockIdx.x] = ssum[0];
        g_count[blockIdx.x]   = scnt[0];
    }
}

__global__ __launch_bounds__(256)
void finalize_kernel(float* __restrict__ loss_out)
{
    __shared__ double sd[256];
    __shared__ double sc[256];
    const int tid = threadIdx.x;
    double s = 0.0, c = 0.0;
    for (int i = tid; i < LOSS_BLOCKS; i += 256) {
        s += (double)g_partial[i];
        c += (double)g_count[i];
    }
    sd[tid] = s; sc[tid] = c;
    __syncthreads();
    for (int off = 128; off > 0; off >>= 1) {
        if (tid < off) { sd[tid] += sd[tid+off]; sc[tid] += sc[tid+off]; }
        __syncthreads();
    }
    if (tid == 0) *loss_out = (float)(sd[0] / fmax(sc[0], 1.0));
}

// ---------------------------------------------------------------------------
extern "C" void kernel_launch(void* const* d_in, const int* in_sizes, int n_in,
                              void* d_out, int out_size)
{
    const float* mask_logits = (const float*)d_in[0];
    const float* stuff_logit = (const float*)d_in[1];
    const float* thing_logit = (const float*)d_in[2];
    const float* bbox        = (const float*)d_in[3];
    const int*   cls_idx     = (const int*)  d_in[4];
    const int*   gt          = (const int*)  d_in[5];

    float* out = (float*)d_out;

    const int total4 = NCH * HW / 4;
    init_kernel<<<(total4 + 255)/256, 256>>>((const float4*)stuff_logit,
                                             (float4*)out);

    dim3 blk(32, 8, 1);
    dim3 grd(4, 13, NI);
    thing_kernel<<<grd, blk>>>(mask_logits, thing_logit, bbox, cls_idx, out);

    loss_kernel<<<LOSS_BLOCKS, 256>>>(out, gt);
    finalize_kernel<<<1, 256>>>(out + (size_t)out_size - 1);
}

// round 4
// speedup vs baseline: 2.5052x; 1.6705x over previous
#include <cuda_runtime.h>
#include <math.h>

#define NI   128
#define Hh   400
#define Ww   400
#define MS   28
#define CT   80
#define CS   53
#define HW   (Hh*Ww)          // 160000
#define NCH  (CS + NI)        // 181
#define HG   1600
#define IGNORE_LBL 255

#define GRID_X 13
#define GRID_Y 50
#define NBLK   (GRID_X*GRID_Y)   // 650

__device__ float g_partial[NBLK];
__device__ float g_count[NBLK];
__device__ unsigned int g_ctr = 0;

// ---------------------------------------------------------------------------
// Fully fused: write pan_logit (stuff copy + thing channels) AND compute the
// per-pixel NLL in one pass. Non-covered thing channels contribute exp(0)=1.
// ---------------------------------------------------------------------------
__global__ __launch_bounds__(256)
void fused_kernel(const float* __restrict__ mask_logits,   // [N,CT,MS,MS]
                  const float* __restrict__ stuff_logit,   // [CS,H,W]
                  const float* __restrict__ thing_logit,   // [CT,H,W]
                  const float* __restrict__ bbox,          // [N,4]
                  const int*   __restrict__ cls_idx,       // [N]
                  const int*   __restrict__ gt,            // [HG,WG]
                  float* __restrict__ out,                 // pan_logit
                  float* __restrict__ loss_out)
{
    __shared__ int   s_x0[NI], s_y0[NI], s_x2[NI], s_y2[NI];
    __shared__ int   s_cx1[NI], s_cy1[NI], s_cx2[NI], s_cy2[NI];
    __shared__ int   s_cls[NI];
    __shared__ float s_syc[NI], s_sxc[NI];
    __shared__ unsigned char s_flag[NI];

    const int tid = threadIdx.y * 32 + threadIdx.x;
    const int bx0 = blockIdx.x * 32;
    const int by0 = blockIdx.y * 8;

    if (tid < NI) {
        const int n = tid;
        const float b0 = bbox[n*4+0], b1 = bbox[n*4+1];
        const float b2 = bbox[n*4+2], b3 = bbox[n*4+3];

        const int x0b = (int)floorf(b0 * 0.25f);
        const int y0b = (int)floorf(b1 * 0.25f);
        const int x2b = (int)floorf(b2 * 0.25f);
        const int y2b = (int)floorf(b3 * 0.25f);
        s_x0[n] = x0b; s_y0[n] = y0b; s_x2[n] = x2b; s_y2[n] = y2b;
        s_syc[n] = (float)MS / (float)(y2b - y0b + 1);
        s_sxc[n] = (float)MS / (float)(x2b - x0b + 1);

        const int cx1 = (int)(b0 * 0.25f);
        const int cy1 = (int)(b1 * 0.25f);
        const int cx2 = (int)(rintf(b2 * 0.25f) + 1.0f);
        const int cy2 = (int)(rintf(b3 * 0.25f) + 1.0f);
        s_cx1[n] = cx1; s_cy1[n] = cy1; s_cx2[n] = cx2; s_cy2[n] = cy2;
        s_cls[n] = cls_idx[n];

        const int rx0 = min(x0b, cx1);
        const int ry0 = min(y0b, cy1);
        const int rx1 = max(x2b, cx2 - 1);
        const int ry1 = max(y2b, cy2 - 1);
        s_flag[n] = (bx0 + 31 >= rx0) && (bx0 <= rx1) &&
                    (by0 + 7  >= ry0) && (by0 <= ry1);
    }
    __syncthreads();

    const int x = bx0 + threadIdx.x;
    const int y = by0 + threadIdx.y;
    const bool active = (x < Ww);

    float contrib = 0.0f, cnt = 0.0f;

    if (active) {
        const int p = y * Ww + x;
        const int g = gt[(size_t)y * 4 * HG + x * 4];
        const int tgt = min(max(g, 0), NCH - 1);

        const float* sp = stuff_logit + p;
        float* op = out + p;

        float sum = 0.0f;
        float tv  = 0.0f;

        // stuff channels: copy + exp accumulate
        #pragma unroll 4
        for (int c = 0; c < CS; ++c) {
            const float v = sp[c * HW];
            op[c * HW] = v;
            sum += __expf(v);
            if (c == tgt) tv = v;
        }

        // thing channels
        const int tgtn = tgt - CS;
        float* opt = op + CS * HW;
        for (int n = 0; n < NI; ++n) {
            if (s_flag[n]) {
                float v = 0.0f;
                const int x0b = s_x0[n], y0b = s_y0[n];
                if (x >= x0b && x <= s_x2[n] && y >= y0b && y <= s_y2[n]) {
                    const float sy = ((float)(y - y0b) + 0.5f) * s_syc[n] - 0.5f;
                    const float fy = floorf(sy);
                    const float ty = sy - fy;
                    int i0 = min(max((int)fy, 0), MS-1);
                    int i1 = min(max((int)fy + 1, 0), MS-1);

                    const float sx = ((float)(x - x0b) + 0.5f) * s_sxc[n] - 0.5f;
                    const float fx = floorf(sx);
                    const float tx = sx - fx;
                    int j0 = min(max((int)fx, 0), MS-1);
                    int j1 = min(max((int)fx + 1, 0), MS-1);

                    const float* ml = mask_logits +
                        ((size_t)n * CT + s_cls[n]) * (MS*MS);
                    const float r00 = ml[i0*MS + j0];
                    const float r10 = ml[i1*MS + j0];
                    const float r01 = ml[i0*MS + j1];
                    const float r11 = ml[i1*MS + j1];
                    const float c0 = r00 * (1.0f - ty) + r10 * ty;
                    const float c1 = r01 * (1.0f - ty) + r11 * ty;
                    v = c0 * (1.0f - tx) + c1 * tx;
                }
                if (x >= s_cx1[n] && x < s_cx2[n] &&
                    y >= s_cy1[n] && y < s_cy2[n]) {
                    v += thing_logit[(size_t)s_cls[n] * HW + p];
                }
                opt[n * HW] = v;
                sum += __expf(v);
                if (n == tgtn) tv = v;
            } else {
                opt[n * HW] = 0.0f;
                sum += 1.0f;
                if (n == tgtn) tv = 0.0f;
            }
        }

        if (g != IGNORE_LBL) {
            contrib = logf(sum) - tv;
            cnt = 1.0f;
        }
    }

    // block reduce (deterministic)
    __shared__ float ssum[256];
    __shared__ float scnt[256];
    ssum[tid] = contrib;
    scnt[tid] = cnt;
    __syncthreads();
    for (int off = 128; off > 0; off >>= 1) {
        if (tid < off) { ssum[tid] += ssum[tid+off]; scnt[tid] += scnt[tid+off]; }
        __syncthreads();
    }

    const int bid = blockIdx.y * GRID_X + blockIdx.x;
    __shared__ bool is_last;
    if (tid == 0) {
        g_partial[bid] = ssum[0];
        g_count[bid]   = scnt[0];
        __threadfence();
        const unsigned int old = atomicAdd(&g_ctr, 1u);
        is_last = (old == NBLK - 1);
        if (is_last) g_ctr = 0;   // reset for next graph replay
    }
    __syncthreads();

    if (is_last) {
        __shared__ double sd[256];
        __shared__ double sc[256];
        double s = 0.0, c = 0.0;
        for (int i = tid; i < NBLK; i += 256) {
            s += (double)g_partial[i];
            c += (double)g_count[i];
        }
        sd[tid] = s; sc[tid] = c;
        __syncthreads();
        for (int off = 128; off > 0; off >>= 1) {
            if (tid < off) { sd[tid] += sd[tid+off]; sc[tid] += sc[tid+off]; }
            __syncthreads();
        }
        if (tid == 0) *loss_out = (float)(sd[0] / fmax(sc[0], 1.0));
    }
}

// ---------------------------------------------------------------------------
extern "C" void kernel_launch(void* const* d_in, const int* in_sizes, int n_in,
                              void* d_out, int out_size)
{
    const float* mask_logits = (const float*)d_in[0];
    const float* stuff_logit = (const float*)d_in[1];
    const float* thing_logit = (const float*)d_in[2];
    const float* bbox        = (const float*)d_in[3];
    const int*   cls_idx     = (const int*)  d_in[4];
    const int*   gt          = (const int*)  d_in[5];

    float* out = (float*)d_out;

    dim3 blk(32, 8, 1);
    dim3 grd(GRID_X, GRID_Y, 1);
    fused_kernel<<<grd, blk>>>(mask_logits, stuff_logit, thing_logit,
                               bbox, cls_idx, gt, out,
                               out + (size_t)out_size - 1);
}